// round 17
// baseline (speedup 1.0000x reference)
#include <cuda_runtime.h>
#include <cuda_bf16.h>
#include <cuda_fp16.h>
#include <math.h>
#include <stdint.h>

#define BB 2
#define LLEN 1024
#define HDIM 1024
#define NHEAD 16
#define HEADD 64
#define DIN 2048
#define NSTATE 16

static const size_t U = (size_t)BB * LLEN * HDIM;  // 2097152

__device__ float g_buf[40304640];

// ===========================================================================
// helpers
// ===========================================================================
__device__ __forceinline__ uint32_t pk_bf2(float lo, float hi) {
    __nv_bfloat162 h = __float22bfloat162_rn(make_float2(lo, hi));
    return *(uint32_t*)&h;
}
__device__ __forceinline__ uint32_t pk_f16(float lo, float hi) {
    __half2 h = __float22half2_rn(make_float2(lo, hi));
    return *(uint32_t*)&h;
}
__device__ __forceinline__ uint32_t ex2pk(float lo, float hi) {
    uint32_t r;
    asm("{\n\t.reg .b32 t;\n\t"
        "cvt.rn.f16x2.f32 t, %1, %2;\n\t"
        "ex2.approx.f16x2 %0, t;\n\t}"
        : "=r"(r) : "f"(hi), "f"(lo));
    return r;
}

#define MMA_BF16(d, a, b) \
    asm volatile( \
        "mma.sync.aligned.m16n8k16.row.col.f32.bf16.bf16.f32 " \
        "{%0,%1,%2,%3}, {%4,%5,%6,%7}, {%8,%9}, {%0,%1,%2,%3};" \
        : "+f"((d)[0]), "+f"((d)[1]), "+f"((d)[2]), "+f"((d)[3]) \
        : "r"((a)[0]), "r"((a)[1]), "r"((a)[2]), "r"((a)[3]), \
          "r"((b)[0]), "r"((b)[1]))

#define MMA_F16(d, a, b) \
    asm volatile( \
        "mma.sync.aligned.m16n8k16.row.col.f32.f16.f16.f32 " \
        "{%0,%1,%2,%3}, {%4,%5,%6,%7}, {%8,%9}, {%0,%1,%2,%3};" \
        : "+f"((d)[0]), "+f"((d)[1]), "+f"((d)[2]), "+f"((d)[3]) \
        : "r"((a)[0]), "r"((a)[1]), "r"((a)[2]), "r"((a)[3]), \
          "r"((b)[0]), "r"((b)[1]))

#define LDSM4(r, addr) \
    asm volatile( \
        "ldmatrix.sync.aligned.m8n8.x4.shared.b16 {%0,%1,%2,%3}, [%4];" \
        : "=r"((r)[0]), "=r"((r)[1]), "=r"((r)[2]), "=r"((r)[3]) \
        : "r"(addr))

#define LDSM4T(r, addr) \
    asm volatile( \
        "ldmatrix.sync.aligned.m8n8.x4.trans.shared.b16 {%0,%1,%2,%3}, [%4];" \
        : "=r"((r)[0]), "=r"((r)[1]), "=r"((r)[2]), "=r"((r)[3]) \
        : "r"(addr))

__device__ __forceinline__ void cp16(uint32_t d, const void* s) {
    asm volatile("cp.async.cg.shared.global [%0], [%1], 16;" :: "r"(d), "l"(s));
}
__device__ __forceinline__ void cp16z(uint32_t d, const void* s, int sz) {
    asm volatile("cp.async.cg.shared.global [%0], [%1], 16, %2;"
                 :: "r"(d), "l"(s), "r"(sz));
}
#define CP_COMMIT() asm volatile("cp.async.commit_group;" ::: "memory")
#define CP_WAIT1()  asm volatile("cp.async.wait_group 1;" ::: "memory")
#define CP_WAIT0()  asm volatile("cp.async.wait_group 0;" ::: "memory")

#define LOG2E 1.44269504f

// ===========================================================================
// f32 -> bf16 conversion (segmented, one launch)
// ===========================================================================
struct CvtSeg { const float* src; __nv_bfloat16* dst; int n; };
struct CvtTab { CvtSeg s[9]; int ns; };

__global__ __launch_bounds__(256) void cvt_kernel(CvtTab tab)
{
    int stride = gridDim.x * blockDim.x * 4;
    for (int seg = 0; seg < tab.ns; seg++) {
        const float* s = tab.s[seg].src;
        __nv_bfloat16* d = tab.s[seg].dst;
        int n = tab.s[seg].n;
        for (int i = (blockIdx.x * blockDim.x + threadIdx.x) * 4; i < n; i += stride) {
            float4 v = *(const float4*)(s + i);
            uint2 o;
            o.x = pk_bf2(v.x, v.y);
            o.y = pk_bf2(v.z, v.w);
            *(uint2*)(d + i) = o;
        }
    }
}

// ===========================================================================
// Templated bf16 tensor GEMM: C[M,N] = A[M,K] @ Bw[N,K]^T
// Tile BM x BN, BK=32 halves, 4-slot ring processed in chunk PAIRS
// (one commit group = 2 chunks, wait_group 1, one barrier per pair).
// act: 0 none, 1 softplus, 2 x(0.125*log2e), 3 emit fp16 to Ch
// ===========================================================================
#define USTR 20

template<int BM, int BN>
__device__ __forceinline__ void mm_body(
    const __nv_bfloat16* __restrict__ A, int lda,
    const __nv_bfloat16* __restrict__ Bw, int ldb,
    const float* __restrict__ bias,
    const float* __restrict__ addsrc,
    float* __restrict__ Cf, __nv_bfloat16* __restrict__ Ch,
    int M, int N, int K, int act, uint32_t* smu)
{
    constexpr int MFRAG = BM / 64;
    constexpr int NFRAG = BN / 16;
    constexpr int NP = NFRAG / 2;
    constexpr int AJ = (BM * 4) / 256;
    constexpr int BJ = (BN * 4) / 256;
    constexpr int SLOTU = (BM + BN) * USTR;

    int t = threadIdx.x;
    int lane = t & 31, wid = t >> 5;
    int wm = wid & 3, wn = wid >> 2;
    int gid = lane >> 2, tig = lane & 3;
    int bm = blockIdx.y * BM, bn = blockIdx.x * BN;

    uint32_t smb = (uint32_t)__cvta_generic_to_shared(smu);

    const __nv_bfloat16* a_src[AJ]; uint32_t a_dst[AJ];
    const __nv_bfloat16* b_src[BJ]; uint32_t b_dst[BJ]; int b_sz[BJ];
#pragma unroll
    for (int j = 0; j < AJ; j++) {
        int i = t + j * 256, row = i >> 2, seg = i & 3;
        a_src[j] = A + (size_t)(bm + row) * lda + seg * 8;
        a_dst[j] = smb + (uint32_t)(row * USTR + seg * 4) * 4;
    }
#pragma unroll
    for (int j = 0; j < BJ; j++) {
        int i = t + j * 256, row = i >> 2, seg = i & 3;
        int gr = bn + row;
        b_sz[j] = (gr < N) ? 16 : 0;
        if (gr >= N) gr = N - 1;
        b_src[j] = Bw + (size_t)gr * ldb + seg * 8;
        b_dst[j] = smb + (uint32_t)((BM + row) * USTR + seg * 4) * 4;
    }

    uint32_t a_ldm[MFRAG], b_ldm[NP];
#pragma unroll
    for (int mm = 0; mm < MFRAG; mm++)
        a_ldm[mm] = smb + (uint32_t)(((wm * (BM / 4) + mm * 16 + (lane & 15)) * USTR
                                      + (lane >> 4) * 4) * 4);
#pragma unroll
    for (int np = 0; np < NP; np++)
        b_ldm[np] = smb + (uint32_t)(((BM + wn * (BN / 2) + np * 16 + (lane & 7)
                                       + ((lane >> 4) & 1) * 8) * USTR
                                      + ((lane >> 3) & 1) * 4) * 4);

    float acc[MFRAG][NFRAG][4];
#pragma unroll
    for (int i = 0; i < MFRAG; i++)
#pragma unroll
        for (int j = 0; j < NFRAG; j++)
#pragma unroll
            for (int q = 0; q < 4; q++) acc[i][j][q] = 0.f;

    int nk = K >> 5;   // always even for our shapes (K in {64, 1024, 2048})

#define ISSUE(c, slot) do { \
        uint32_t off = (uint32_t)(slot) * (SLOTU * 4); \
        int k0 = (c) << 5; \
        _Pragma("unroll") \
        for (int j = 0; j < AJ; j++) cp16(a_dst[j] + off, a_src[j] + k0); \
        _Pragma("unroll") \
        for (int j = 0; j < BJ; j++) cp16z(b_dst[j] + off, b_src[j] + k0, b_sz[j]); \
    } while (0)

#define COMPUTE_SLOT(slot) do { \
        uint32_t soff = (uint32_t)(slot) * (SLOTU * 4); \
        _Pragma("unroll") \
        for (int ks = 0; ks < 2; ks++) { \
            uint32_t koff = soff + ks * 32; \
            uint32_t af[MFRAG][4]; \
            _Pragma("unroll") \
            for (int mm = 0; mm < MFRAG; mm++) \
                LDSM4(af[mm], a_ldm[mm] + koff); \
            uint32_t bf[NP][4]; \
            _Pragma("unroll") \
            for (int np = 0; np < NP; np++) \
                LDSM4(bf[np], b_ldm[np] + koff); \
            _Pragma("unroll") \
            for (int mm = 0; mm < MFRAG; mm++) \
                _Pragma("unroll") \
                for (int nn = 0; nn < NFRAG; nn++) \
                    MMA_BF16(acc[mm][nn], af[mm], &bf[nn >> 1][(nn & 1) * 2]); \
        } \
    } while (0)

    // prologue: pair P0 -> slots {0,1}, pair P1 -> slots {2,3}
    ISSUE(0, 0);
    if (1 < nk) ISSUE(1, 1);
    CP_COMMIT();
    if (2 < nk) ISSUE(2, 2);
    if (3 < nk) ISSUE(3, 3);
    CP_COMMIT();
    CP_WAIT1();
    __syncthreads();

    int npairs = nk >> 1;
    for (int p = 0; p < npairs; p++) {
        int s0 = (p & 1) * 2;
        COMPUTE_SLOT(s0);
        COMPUTE_SLOT(s0 + 1);
        int cn = 2 * p + 4;
        if (cn < nk) {
            ISSUE(cn, s0);
            if (cn + 1 < nk) ISSUE(cn + 1, s0 + 1);
        }
        CP_COMMIT();
        CP_WAIT1();
        __syncthreads();
    }
#undef ISSUE
#undef COMPUTE_SLOT

#pragma unroll
    for (int mm = 0; mm < MFRAG; mm++) {
        int r0 = bm + wm * (BM / 4) + mm * 16 + gid;
#pragma unroll
        for (int nn = 0; nn < NFRAG; nn++) {
            int col = bn + wn * (BN / 2) + nn * 8 + 2 * tig;
            if (col < N) {
                float v00 = acc[mm][nn][0], v01 = acc[mm][nn][1];
                float v10 = acc[mm][nn][2], v11 = acc[mm][nn][3];
                if (bias) {
                    float b0 = bias[col], b1 = bias[col + 1];
                    v00 += b0; v01 += b1; v10 += b0; v11 += b1;
                }
                size_t o0 = (size_t)r0 * N + col;
                size_t o1 = (size_t)(r0 + 8) * N + col;
                if (addsrc) {
                    v00 += addsrc[o0]; v01 += addsrc[o0 + 1];
                    v10 += addsrc[o1]; v11 += addsrc[o1 + 1];
                }
                if (act == 1) {
                    v00 = (v00 > 20.f) ? v00 : log1pf(__expf(v00));
                    v01 = (v01 > 20.f) ? v01 : log1pf(__expf(v01));
                    v10 = (v10 > 20.f) ? v10 : log1pf(__expf(v10));
                    v11 = (v11 > 20.f) ? v11 : log1pf(__expf(v11));
                } else if (act == 2) {
                    const float s = 0.125f * LOG2E;
                    v00 *= s; v01 *= s; v10 *= s; v11 *= s;
                }
                if (Cf) {
                    *(float2*)(Cf + o0) = make_float2(v00, v01);
                    *(float2*)(Cf + o1) = make_float2(v10, v11);
                }
                if (Ch) {
                    if (act == 3) {
                        *(uint32_t*)(Ch + o0) = pk_f16(v00, v01);
                        *(uint32_t*)(Ch + o1) = pk_f16(v10, v11);
                    } else {
                        *(uint32_t*)(Ch + o0) = pk_bf2(v00, v01);
                        *(uint32_t*)(Ch + o1) = pk_bf2(v10, v11);
                    }
                }
            }
        }
    }
}

template<int BM, int BN>
__global__ __launch_bounds__(256, 2) void mm_kernel(
    const __nv_bfloat16* __restrict__ A, int lda,
    const __nv_bfloat16* __restrict__ Bw, int ldb,
    const float* __restrict__ bias,
    const float* __restrict__ addsrc,
    float* __restrict__ Cf, __nv_bfloat16* __restrict__ Ch,
    int M, int N, int K, int act)
{
    extern __shared__ uint32_t smu[];
    mm_body<BM, BN>(A, lda, Bw, ldb, bias, addsrc, Cf, Ch, M, N, K, act, smu);
}

struct Tri {
    const __nv_bfloat16* W[3];
    const float* b[3];
    float* Cf[3];
    __nv_bfloat16* Ch[3];
    int act[3];
};

template<int BM, int BN>
__global__ __launch_bounds__(256, 2) void mm3_kernel(
    const __nv_bfloat16* __restrict__ A, int lda, Tri tri, int ldb,
    int M, int N, int K)
{
    extern __shared__ uint32_t smu[];
    int z = blockIdx.z;
    mm_body<BM, BN>(A, lda, tri.W[z], ldb, tri.b[z], nullptr,
                    tri.Cf[z], tri.Ch[z], M, N, K, tri.act[z], smu);
}

#define MM_SMEM_128_64 (4 * (128 + 64) * USTR * 4)   // 61440
#define MM_SMEM_64_64  (4 * (64 + 64) * USTR * 4)    // 40960

// ===========================================================================
// Flash attention v3: 256 threads = 8 warps = 128 q rows/block.
// cp.async double-buffered K/V/mask staging; ldmatrix frags; fp16 P/V O-MMA.
// ===========================================================================
#define KSTR 36
#define VSTR 36
#define KVSLOT (64 * KSTR)
#define FA_SMEM ((4 * KVSLOT + 128) * 4)      // 37376 B

__global__ __launch_bounds__(256) void fattn_kernel(
    const __nv_bfloat16* __restrict__ q, const __nv_bfloat16* __restrict__ k,
    const __half* __restrict__ v, const int* __restrict__ mask,
    __nv_bfloat16* __restrict__ ctx)
{
    extern __shared__ uint32_t su[];
    uint32_t* KsU = su;
    int* MsI = (int*)(su + 4 * KVSLOT);

    int t = threadIdx.x;
    int lane = t & 31, wid = t >> 5;
    int gid = lane >> 2, tig = lane & 3;
    int q0 = blockIdx.x * 128;
    int h = blockIdx.y, b = blockIdx.z;
    size_t base = ((size_t)b * LLEN) * HDIM + h * HEADD;

    uint32_t smb = (uint32_t)__cvta_generic_to_shared(su);
    uint32_t smbV = smb + 2 * KVSLOT * 4;
    uint32_t smbM = smb + 4 * KVSLOT * 4;

    uint32_t kb_ldm[4], vb_ldm[4];
#pragma unroll
    for (int np = 0; np < 4; np++) {
        kb_ldm[np] = smb + (uint32_t)(((np * 16 + (lane & 7) + ((lane >> 4) & 1) * 8) * KSTR
                                       + ((lane >> 3) & 1) * 4) * 4);
        vb_ldm[np] = smbV + (uint32_t)(((lane & 15) * VSTR
                                        + np * 8 + ((lane >> 4) & 1) * 4) * 4);
    }

    for (int j = 0; j < 4; j++) {
        int i = t + j * 256;
        int row = i >> 3, c = i & 7;
        uint4 qv = *(const uint4*)(q + base + (size_t)(q0 + row) * HDIM + c * 8);
        *(uint4*)(KsU + (row >> 6) * KVSLOT + (row & 63) * KSTR + c * 4) = qv;
    }
    __syncthreads();
    int r0 = wid * 16 + gid;
    const uint32_t* Qb = KsU + (wid >> 2) * KVSLOT;
    int qr = r0 & 63;
    uint32_t aq[4][4];
#pragma unroll
    for (int ks = 0; ks < 4; ks++) {
        aq[ks][0] = Qb[qr * KSTR + ks * 8 + tig];
        aq[ks][1] = Qb[(qr + 8) * KSTR + ks * 8 + tig];
        aq[ks][2] = Qb[qr * KSTR + ks * 8 + tig + 4];
        aq[ks][3] = Qb[(qr + 8) * KSTR + ks * 8 + tig + 4];
    }
    __syncthreads();

    float m_i[2] = {-1e30f, -1e30f};
    float oacc[8][4];
    float lacc[4] = {0.f, 0.f, 0.f, 0.f};
#pragma unroll
    for (int nt = 0; nt < 8; nt++)
#pragma unroll
        for (int qq = 0; qq < 4; qq++) oacc[nt][qq] = 0.f;

    const uint32_t one2 = 0x3C003C00u;

#define STAGE_KV(kv0, slot) do { \
        uint32_t koff = smb + (uint32_t)(slot) * (KVSLOT * 4); \
        uint32_t voff = smbV + (uint32_t)(slot) * (KVSLOT * 4); \
        _Pragma("unroll") \
        for (int j = 0; j < 2; j++) { \
            int i = t + j * 256; \
            int row = i >> 3, c = i & 7; \
            cp16(koff + (uint32_t)(row * KSTR + c * 4) * 4, \
                 k + base + (size_t)((kv0) + row) * HDIM + c * 8); \
            cp16(voff + (uint32_t)(row * VSTR + c * 4) * 4, \
                 v + base + (size_t)((kv0) + row) * HDIM + c * 8); \
        } \
        if (t < 16) \
            cp16(smbM + (uint32_t)(slot) * 256 + t * 16, \
                 mask + b * LLEN + (kv0) + t * 4); \
    } while (0)

    STAGE_KV(0, 0);
    CP_COMMIT();

    for (int it = 0; it < LLEN / 64; it++) {
        int slot = it & 1;
        if (it + 1 < LLEN / 64) {
            STAGE_KV((it + 1) * 64, slot ^ 1);
            CP_COMMIT();
            CP_WAIT1();
        } else {
            CP_WAIT0();
        }
        __syncthreads();

        uint32_t kvoff = (uint32_t)slot * (KVSLOT * 4);
        const int* Mc = MsI + slot * 64;

        float sacc[8][4];
#pragma unroll
        for (int nt = 0; nt < 8; nt++)
#pragma unroll
            for (int qq = 0; qq < 4; qq++) sacc[nt][qq] = 0.f;
#pragma unroll
        for (int ks = 0; ks < 4; ks++) {
            uint32_t kf[4][4];
#pragma unroll
            for (int np = 0; np < 4; np++)
                LDSM4(kf[np], kb_ldm[np] + kvoff + ks * 32);
#pragma unroll
            for (int nt = 0; nt < 8; nt++)
                MMA_BF16(sacc[nt], aq[ks], &kf[nt >> 1][(nt & 1) * 2]);
        }

        float mnew0 = m_i[0], mnew1 = m_i[1];
#pragma unroll
        for (int nt = 0; nt < 8; nt++) {
            float mk0 = (float)Mc[nt * 8 + 2 * tig] * LOG2E;
            float mk1 = (float)Mc[nt * 8 + 2 * tig + 1] * LOG2E;
            sacc[nt][0] += mk0; sacc[nt][1] += mk1;
            sacc[nt][2] += mk0; sacc[nt][3] += mk1;
            mnew0 = fmaxf(mnew0, fmaxf(sacc[nt][0], sacc[nt][1]));
            mnew1 = fmaxf(mnew1, fmaxf(sacc[nt][2], sacc[nt][3]));
        }
        mnew0 = fmaxf(mnew0, __shfl_xor_sync(0xffffffffu, mnew0, 1));
        mnew0 = fmaxf(mnew0, __shfl_xor_sync(0xffffffffu, mnew0, 2));
        mnew1 = fmaxf(mnew1, __shfl_xor_sync(0xffffffffu, mnew1, 1));
        mnew1 = fmaxf(mnew1, __shfl_xor_sync(0xffffffffu, mnew1, 2));

        float sc0 = exp2f(m_i[0] - mnew0);
        float sc1 = exp2f(m_i[1] - mnew1);
        m_i[0] = mnew0; m_i[1] = mnew1;

#pragma unroll
        for (int nt = 0; nt < 8; nt++) {
            oacc[nt][0] *= sc0; oacc[nt][1] *= sc0;
            oacc[nt][2] *= sc1; oacc[nt][3] *= sc1;
        }
        lacc[0] *= sc0; lacc[1] *= sc0;
        lacc[2] *= sc1; lacc[3] *= sc1;

#pragma unroll
        for (int g = 0; g < 4; g++) {
            uint32_t ap[4];
            ap[0] = ex2pk(sacc[2 * g][0] - mnew0, sacc[2 * g][1] - mnew0);
            ap[1] = ex2pk(sacc[2 * g][2] - mnew1, sacc[2 * g][3] - mnew1);
            ap[2] = ex2pk(sacc[2 * g + 1][0] - mnew0, sacc[2 * g + 1][1] - mnew0);
            ap[3] = ex2pk(sacc[2 * g + 1][2] - mnew1, sacc[2 * g + 1][3] - mnew1);
            uint32_t voff = kvoff + (uint32_t)(g * 16 * VSTR * 4);
#pragma unroll
            for (int np = 0; np < 4; np++) {
                uint32_t vf[4];
                LDSM4T(vf, vb_ldm[np] + voff);
                MMA_F16(oacc[np * 2], ap, &vf[0]);
                MMA_F16(oacc[np * 2 + 1], ap, &vf[2]);
            }
            uint32_t bone[2] = {one2, one2};
            MMA_F16(lacc, ap, bone);
        }
        __syncthreads();
    }
#undef STAGE_KV

    float inv0 = 1.f / lacc[0], inv1 = 1.f / lacc[2];
#pragma unroll
    for (int nt = 0; nt < 8; nt++) {
        int col = nt * 8 + 2 * tig;
        *(uint32_t*)(ctx + base + (size_t)(q0 + r0) * HDIM + col) =
            pk_bf2(oacc[nt][0] * inv0, oacc[nt][1] * inv0);
        *(uint32_t*)(ctx + base + (size_t)(q0 + r0 + 8) * HDIM + col) =
            pk_bf2(oacc[nt][2] * inv1, oacc[nt][3] * inv1);
    }
}

// ---------------------------------------------------------------------------
// Row reductions
// ---------------------------------------------------------------------------
__device__ __forceinline__ float block_sum_256(float v, float* sh)
{
#pragma unroll
    for (int o = 16; o; o >>= 1) v += __shfl_xor_sync(0xffffffffu, v, o);
    int lane = threadIdx.x & 31, w = threadIdx.x >> 5;
    if (lane == 0) sh[w] = v;
    __syncthreads();
    if (threadIdx.x == 0) {
        float r = sh[0];
#pragma unroll
        for (int i = 1; i < 8; i++) r += sh[i];
        sh[8] = r;
    }
    __syncthreads();
    float r = sh[8];
    __syncthreads();
    return r;
}

__global__ __launch_bounds__(256) void ln_rms_kernel(
    const float* __restrict__ tin, const float* __restrict__ hidden,
    const float* __restrict__ lnw, const float* __restrict__ lnb,
    const float* __restrict__ mnw,
    float* __restrict__ x2, __nv_bfloat16* __restrict__ hout)
{
    __shared__ float sh[9];
    size_t row = blockIdx.x;
    int tid = threadIdx.x;
    const float* tp = tin + row * HDIM;
    float v[4]; float s = 0.f;
#pragma unroll
    for (int i = 0; i < 4; i++) { v[i] = tp[tid + 256 * i]; s += v[i]; }
    s = block_sum_256(s, sh);
    float mu = s * (1.f / 1024.f);
    float vs = 0.f;
#pragma unroll
    for (int i = 0; i < 4; i++) { float dd = v[i] - mu; vs += dd * dd; }
    vs = block_sum_256(vs, sh);
    float rstd = rsqrtf(vs * (1.f / 1024.f) + 1e-12f);
    float xv[4]; float ss = 0.f;
#pragma unroll
    for (int i = 0; i < 4; i++) {
        int c = tid + 256 * i;
        float z = (v[i] - mu) * rstd * lnw[c] + lnb[c] + hidden[row * HDIM + c];
        xv[i] = z; x2[row * HDIM + c] = z; ss += z * z;
    }
    ss = block_sum_256(ss, sh);
    float rr = rsqrtf(ss * (1.f / 1024.f) + 1e-6f);
#pragma unroll
    for (int i = 0; i < 4; i++) {
        int c = tid + 256 * i;
        hout[row * HDIM + c] = __float2bfloat16(xv[i] * rr * mnw[c]);
    }
}

__global__ __launch_bounds__(256) void rms_kernel(
    const float* __restrict__ x, const float* __restrict__ w,
    float* __restrict__ out)
{
    __shared__ float sh[9];
    size_t row = blockIdx.x;
    int tid = threadIdx.x;
    const float* xp = x + row * HDIM;
    float v[4]; float ss = 0.f;
#pragma unroll
    for (int i = 0; i < 4; i++) { v[i] = xp[tid + 256 * i]; ss += v[i] * v[i]; }
    ss = block_sum_256(ss, sh);
    float rr = rsqrtf(ss * (1.f / 1024.f) + 1e-6f);
#pragma unroll
    for (int i = 0; i < 4; i++) {
        int c = tid + 256 * i;
        out[row * HDIM + c] = v[i] * rr * w[c];
    }
}

// ---------------------------------------------------------------------------
// Depthwise causal conv (K=4) + SiLU + mask, halo reuse (4 outputs/thread)
// ---------------------------------------------------------------------------
__global__ __launch_bounds__(256) void conv_kernel(
    const float* __restrict__ proj, const int* __restrict__ mask,
    const float* __restrict__ cw, const float* __restrict__ cb,
    float* __restrict__ ssm, __nv_bfloat16* __restrict__ ssm_h)
{
    int idx = blockIdx.x * 256 + threadIdx.x;
    int d = idx & (DIN - 1);
    int l4 = (idx >> 11) & 255;
    int b = idx >> 19;
    int l0 = l4 * 4;

    float w0 = cw[d * 4], w1 = cw[d * 4 + 1];
    float w2 = cw[d * 4 + 2], w3 = cw[d * 4 + 3];
    float bias = cb[d];

    float x[7];
#pragma unroll
    for (int j = 0; j < 7; j++) {
        int lp = l0 - 3 + j;
        x[j] = (lp >= 0)
            ? proj[((size_t)(b * LLEN + lp)) * (2 * DIN) + d] * (float)mask[b * LLEN + lp]
            : 0.f;
    }
#pragma unroll
    for (int o = 0; o < 4; o++) {
        float acc = bias;
        acc = fmaf(x[o], w0, acc);
        acc = fmaf(x[o + 1], w1, acc);
        acc = fmaf(x[o + 2], w2, acc);
        acc = fmaf(x[o + 3], w3, acc);
        float sv = acc / (1.f + __expf(-acc));
        float oo = sv * (float)mask[b * LLEN + l0 + o];
        size_t oi = ((size_t)(b * LLEN + l0 + o)) * DIN + d;
        ssm[oi] = oo;
        ssm_h[oi] = __float2bfloat16(oo);
    }
}

// ---------------------------------------------------------------------------
// Chunked 2-pass selective scan: 4 chunks of 256.
// ---------------------------------------------------------------------------
#define NCH 4
#define CLEN 256

__global__ __launch_bounds__(256) void scan1_kernel(
    const float* __restrict__ dt, const float* __restrict__ dbc,
    const float* __restrict__ u, const float* __restrict__ Alog,
    float* __restrict__ Sbuf, float* __restrict__ Pbuf)
{
    int t = threadIdx.x;
    int lane = t & 31;
    int n = lane & 15, g = lane >> 4, w = t >> 5;
    int blk = blockIdx.x & 127;
    int b = (blockIdx.x >> 7) & 1;
    int ch = blockIdx.x >> 8;
    int d = blk * 16 + w * 2 + g;
    float aA2 = -__expf(Alog[d * NSTATE + n]) * LOG2E;
    float s = 0.f, P = 1.f;
    size_t tok = (size_t)b * LLEN + ch * CLEN;

    for (int l0 = 0; l0 < CLEN; l0 += 4) {
#pragma unroll
        for (int j = 0; j < 4; j++) {
            size_t row = tok + l0 + j;
            float dtv = dt[row * DIN + d];
            float uv = u[row * DIN + d];
            float Bv = dbc[row * 96 + 64 + n];
            float dA = exp2f(dtv * aA2);
            s = fmaf(dA, s, dtv * uv * Bv);
            P *= dA;
        }
    }
    int si = ((ch * BB + b) * DIN + d) * 16 + n;
    Sbuf[si] = s;
    Pbuf[si] = P;
}

__global__ __launch_bounds__(256) void scan2_kernel(
    const float* __restrict__ dt, const float* __restrict__ dbc,
    const float* __restrict__ u, const float* __restrict__ proj,
    const float* __restrict__ Alog, const float* __restrict__ Dskip,
    const float* __restrict__ Sbuf, const float* __restrict__ Pbuf,
    __nv_bfloat16* __restrict__ outp)
{
    int t = threadIdx.x;
    int lane = t & 31;
    int n = lane & 15, g = lane >> 4, w = t >> 5;
    int blk = blockIdx.x & 127;
    int b = (blockIdx.x >> 7) & 1;
    int ch = blockIdx.x >> 8;
    int d = blk * 16 + w * 2 + g;
    float aA2 = -__expf(Alog[d * NSTATE + n]) * LOG2E;
    float dsk = Dskip[d];

    float s = 0.f;
    for (int cc = 0; cc < ch; cc++) {
        int si = ((cc * BB + b) * DIN + d) * 16 + n;
        s = Sbuf[si] + Pbuf[si] * s;
    }

    size_t tok = (size_t)b * LLEN + ch * CLEN;

    float rdt[2][4], ru[2][4], rg[2][4], rB[2][4], rC[2][4];

#define LOADG(ph, l0) do { \
    _Pragma("unroll") \
    for (int j = 0; j < 4; j++) { \
        size_t row = tok + (l0) + j; \
        rdt[ph][j] = dt[row * DIN + d]; \
        ru[ph][j]  = u[row * DIN + d]; \
        rg[ph][j]  = proj[row * (2 * DIN) + DIN + d]; \
        rB[ph][j]  = dbc[row * 96 + 64 + n]; \
        rC[ph][j]  = dbc[row * 96 + 80 + n]; \
    } } while (0)

    LOADG(0, 0);
    for (int l0 = 0; l0 < CLEN; l0 += 4) {
        int ph = (l0 >> 2) & 1;
        if (l0 + 4 < CLEN) LOADG(ph ^ 1, l0 + 4);
#pragma unroll
        for (int j = 0; j < 4; j++) {
            float dtv = rdt[ph][j];
            float dA = exp2f(dtv * aA2);
            s = fmaf(dA, s, dtv * ru[ph][j] * rB[ph][j]);
            float p = s * rC[ph][j];
            p += __shfl_xor_sync(0xffffffffu, p, 1);
            p += __shfl_xor_sync(0xffffffffu, p, 2);
            p += __shfl_xor_sync(0xffffffffu, p, 4);
            p += __shfl_xor_sync(0xffffffffu, p, 8);
            if (n == 0) {
                float gv = rg[ph][j];
                float sg = gv / (1.f + __expf(-gv));
                float o = (p + ru[ph][j] * dsk) * sg;
                outp[(tok + l0 + j) * DIN + d] = __float2bfloat16(o);
            }
        }
    }
#undef LOADG
}

// ---------------------------------------------------------------------------
extern "C" void kernel_launch(void* const* d_in, const int* in_sizes, int n_in,
                              void* d_out, int out_size)
{
    const float* hidden = (const float*)d_in[0];
    const int*   mask   = (const int*)d_in[1];
    const float* Wq = (const float*)d_in[2];
    const float* bq = (const float*)d_in[3];
    const float* Wk = (const float*)d_in[4];
    const float* bk = (const float*)d_in[5];
    const float* Wv = (const float*)d_in[6];
    const float* bv = (const float*)d_in[7];
    const float* Wo = (const float*)d_in[8];
    const float* bo = (const float*)d_in[9];
    const float* lnw = (const float*)d_in[10];
    const float* lnb = (const float*)d_in[11];
    const float* mnw = (const float*)d_in[12];
    const float* inpw = (const float*)d_in[13];
    const float* convw = (const float*)d_in[14];
    const float* convb = (const float*)d_in[15];
    const float* xpw = (const float*)d_in[16];
    const float* dtpw = (const float*)d_in[17];
    const float* dtpb = (const float*)d_in[18];
    const float* Alog = (const float*)d_in[19];
    const float* Dsk = (const float*)d_in[20];
    const float* outpw = (const float*)d_in[21];
    const float* fnw = (const float*)d_in[22];
    float* out = (float*)d_out;

    float* buf = nullptr;
    cudaGetSymbolAddress((void**)&buf, g_buf);

    __half* vb_h = (__half*)buf;
    float* tb   = buf + U;
    float* x2   = buf + 2 * U;
    float* proj = buf + 3 * U;
    float* ssm  = buf + 7 * U;
    float* dtb  = buf + 9 * U;
    float* xf   = buf + 11 * U;
    float* dbc  = buf + 12 * U;
    float* Sbuf = tb;
    float* Pbuf = tb + 196608;
    float* hreg = buf + 12 * U + 196608;
    __nv_bfloat16* hidden_h = (__nv_bfloat16*)hreg;
    __nv_bfloat16* qb_h  = (__nv_bfloat16*)(hreg + 1048576);
    __nv_bfloat16* kb_h  = (__nv_bfloat16*)(hreg + 2097152);
    __nv_bfloat16* ctx_h = (__nv_bfloat16*)(hreg + 3145728);
    __nv_bfloat16* hb_h  = (__nv_bfloat16*)(hreg + 4194304);
    __nv_bfloat16* ssm_h = (__nv_bfloat16*)(hreg + 5242880);
    __nv_bfloat16* scan_h = (__nv_bfloat16*)(hreg + 7340032);
    __nv_bfloat16* dbc_h = (__nv_bfloat16*)(hreg + 9437184);
    __nv_bfloat16* w_h   = (__nv_bfloat16*)(hreg + 9535488);
    __nv_bfloat16* wq_h  = w_h;
    __nv_bfloat16* wk_h  = w_h + 1048576;
    __nv_bfloat16* wv_h  = w_h + 2097152;
    __nv_bfloat16* wo_h  = w_h + 3145728;
    __nv_bfloat16* inp_h = w_h + 4194304;
    __nv_bfloat16* xp_h  = w_h + 8388608;
    __nv_bfloat16* dtp_h = w_h + 8585216;
    __nv_bfloat16* outp_h = w_h + 8716288;

    int M = BB * LLEN;
    dim3 thr(256);

    cudaFuncSetAttribute(mm_kernel<128, 64>, cudaFuncAttributeMaxDynamicSharedMemorySize, MM_SMEM_128_64);
    cudaFuncSetAttribute(mm_kernel<64, 64>, cudaFuncAttributeMaxDynamicSharedMemorySize, MM_SMEM_64_64);
    cudaFuncSetAttribute(mm3_kernel<128, 64>, cudaFuncAttributeMaxDynamicSharedMemorySize, MM_SMEM_128_64);
    cudaFuncSetAttribute(fattn_kernel, cudaFuncAttributeMaxDynamicSharedMemorySize, FA_SMEM);

    // launch #1: convert weights + hidden to bf16
    CvtTab tab;
    tab.ns = 9;
    tab.s[0] = {hidden, hidden_h, (int)U};
    tab.s[1] = {Wq, wq_h, 1048576};
    tab.s[2] = {Wk, wk_h, 1048576};
    tab.s[3] = {Wv, wv_h, 1048576};
    tab.s[4] = {Wo, wo_h, 1048576};
    tab.s[5] = {inpw, inp_h, 4194304};
    tab.s[6] = {xpw, xp_h, 196608};
    tab.s[7] = {dtpw, dtp_h, 131072};
    tab.s[8] = {outpw, outp_h, 2097152};
    cvt_kernel<<<1024, thr>>>(tab);

    // launch #2: QKV
    Tri tri;
    tri.W[0] = wq_h; tri.W[1] = wk_h; tri.W[2] = wv_h;
    tri.b[0] = bq;   tri.b[1] = bk;   tri.b[2] = bv;
    tri.Cf[0] = nullptr; tri.Cf[1] = nullptr; tri.Cf[2] = nullptr;
    tri.Ch[0] = qb_h;    tri.Ch[1] = kb_h;    tri.Ch[2] = (__nv_bfloat16*)vb_h;
    tri.act[0] = 2; tri.act[1] = 0; tri.act[2] = 3;
    mm3_kernel<128, 64><<<dim3(16, 16, 3), thr, MM_SMEM_128_64>>>(hidden_h, HDIM, tri, HDIM, M, HDIM, HDIM);

    // launch #3: attention
    fattn_kernel<<<dim3(LLEN / 128, NHEAD, BB), thr, FA_SMEM>>>(qb_h, kb_h, vb_h, mask, ctx_h);

    // launch #4: Wo GEMM (profiled)
    mm_kernel<128, 64><<<dim3(16, 16), thr, MM_SMEM_128_64>>>(ctx_h, HDIM, wo_h, HDIM, bo, hidden, tb, nullptr, M, HDIM, HDIM, 0);

    ln_rms_kernel<<<M, thr>>>(tb, hidden, lnw, lnb, mnw, x2, hb_h);

    mm_kernel<128, 64><<<dim3(64, 16), thr, MM_SMEM_128_64>>>(hb_h, HDIM, inp_h, HDIM, nullptr, nullptr, proj, nullptr, M, 2 * DIN, HDIM, 0);

    conv_kernel<<<(BB * (LLEN / 4) * DIN) / 256, thr>>>(proj, mask, convw, convb, ssm, ssm_h);

    mm_kernel<64, 64><<<dim3(2, 32), thr, MM_SMEM_64_64>>>(ssm_h, DIN, xp_h, DIN, nullptr, nullptr, dbc, dbc_h, M, 96, DIN, 0);

    mm_kernel<128, 64><<<dim3(32, 16), thr, MM_SMEM_128_64>>>(dbc_h, 96, dtp_h, 64, dtpb, nullptr, dtb, nullptr, M, DIN, 64, 1);

    scan1_kernel<<<(NCH - 1) * 256, thr>>>(dtb, dbc, ssm, Alog, Sbuf, Pbuf);
    scan2_kernel<<<NCH * 256, thr>>>(dtb, dbc, ssm, proj, Alog, Dsk, Sbuf, Pbuf, scan_h);

    mm_kernel<128, 64><<<dim3(16, 16), thr, MM_SMEM_128_64>>>(scan_h, DIN, outp_h, DIN, nullptr, x2, xf, nullptr, M, HDIM, DIN, 0);

    rms_kernel<<<M, thr>>>(xf, fnw, out);
}